// round 8
// baseline (speedup 1.0000x reference)
#include <cuda_runtime.h>
#include <math.h>

// Problem constants (fixed by the reference)
#define T_TOK 8192
#define H_DIM 2048
#define F_DIM 1408
#define E_NUM 8
#define F2    (2 * F_DIM)

// ---------------------------------------------------------------------------
// Static device scratch (no allocation allowed anywhere)
// ---------------------------------------------------------------------------
__device__ int   g_cnt[E_NUM];                                   // tokens per expert
__device__ int   g_tok[E_NUM * T_TOK];                           // token id per slot
__device__ float g_wgt[E_NUM * T_TOK];                           // routing weight per slot
__device__ float g_act[(long long)E_NUM * T_TOK * F_DIM];        // silu(gate)*up per slot

// ---------------------------------------------------------------------------
// Kernel 0: zero the output and the expert counters (runs every replay)
// ---------------------------------------------------------------------------
__global__ void init_kernel(float* __restrict__ out) {
    int idx = blockIdx.x * blockDim.x + threadIdx.x;
    if (idx < E_NUM) g_cnt[idx] = 0;
    const long long n = (long long)T_TOK * H_DIM;
    long long stride = (long long)gridDim.x * blockDim.x;
    for (long long i = idx; i < n; i += stride) out[i] = 0.0f;
}

// ---------------------------------------------------------------------------
// Kernel 1: softmax + top-2 routing, gather tokens per expert
// ---------------------------------------------------------------------------
__global__ void route_kernel(const float* __restrict__ logits) {
    int t = blockIdx.x * blockDim.x + threadIdx.x;
    if (t >= T_TOK) return;

    float l[E_NUM];
#pragma unroll
    for (int i = 0; i < E_NUM; i++) l[i] = logits[t * E_NUM + i];

    // top-1 (ties -> lower index, strict > keeps earliest)
    int   i0 = 0;
    float v0 = l[0];
#pragma unroll
    for (int i = 1; i < E_NUM; i++) {
        if (l[i] > v0) { v0 = l[i]; i0 = i; }
    }
    // top-2
    int   i1 = -1;
    float v1 = -3.402823466e+38f;
#pragma unroll
    for (int i = 0; i < E_NUM; i++) {
        if (i != i0 && l[i] > v1) { v1 = l[i]; i1 = i; }
    }

    // normalized top-2 softmax weights: w0 = e^{v0} / (e^{v0} + e^{v1})
    float r  = expf(v1 - v0);          // <= 1, stable
    float w0 = 1.0f / (1.0f + r);
    float w1 = r / (1.0f + r);

    int p0 = atomicAdd(&g_cnt[i0], 1);
    g_tok[i0 * T_TOK + p0] = t;
    g_wgt[i0 * T_TOK + p0] = w0;

    int p1 = atomicAdd(&g_cnt[i1], 1);
    g_tok[i1 * T_TOK + p1] = t;
    g_wgt[i1 * T_TOK + p1] = w1;
}

// ---------------------------------------------------------------------------
// Kernel 2: GEMM1 (gathered A) + fused SiLU*up
//   Per block: 128 token-slots x (64 gate cols + 64 up cols), K = H_DIM.
//   grid = (T/128, F/64, E); early-exit on empty M tiles.
// ---------------------------------------------------------------------------
__global__ __launch_bounds__(256, 2)
void gemm1_kernel(const float* __restrict__ hidden, const float* __restrict__ w1) {
    const int e   = blockIdx.z;
    const int cnt = g_cnt[e];
    const int m0  = blockIdx.x * 128;
    if (m0 >= cnt) return;
    const int n0  = blockIdx.y * 64;

    __shared__ float As[16 * 132];   // [k][row], padded
    __shared__ float Bg[16 * 68];    // [k][n], gate rows
    __shared__ float Bu[16 * 68];    // [k][n], up rows
    __shared__ int   stok[128];

    const int tid = threadIdx.x;
    const int tx  = tid & 15;        // 0..15  -> 4 cols each (gate & up)
    const int ty  = tid >> 4;        // 0..15  -> 8 rows each

    if (tid < 128) {
        int i = m0 + tid;
        stok[tid] = (i < cnt) ? g_tok[e * T_TOK + i] : 0;
    }
    __syncthreads();

    float accg[8][4];
    float accu[8][4];
#pragma unroll
    for (int i = 0; i < 8; i++)
#pragma unroll
        for (int j = 0; j < 4; j++) { accg[i][j] = 0.0f; accu[i][j] = 0.0f; }

    const float* w1g = w1 + (size_t)e * F2 * H_DIM + (size_t)n0 * H_DIM;
    const float* w1u = w1g + (size_t)F_DIM * H_DIM;

    const int lr  = tid >> 2;          // 0..63
    const int lk4 = (tid & 3) * 4;     // 0,4,8,12

    for (int k0 = 0; k0 < H_DIM; k0 += 16) {
        // ---- A tile: 128 rows x 16 k (gathered) ----
#pragma unroll
        for (int r = 0; r < 2; r++) {
            int row = lr + r * 64;
            float4 v = *(const float4*)(hidden + (size_t)stok[row] * H_DIM + k0 + lk4);
            As[(lk4 + 0) * 132 + row] = v.x;
            As[(lk4 + 1) * 132 + row] = v.y;
            As[(lk4 + 2) * 132 + row] = v.z;
            As[(lk4 + 3) * 132 + row] = v.w;
        }
        // ---- B tiles: 64 rows x 16 k, gate and up ----
        {
            float4 vg = *(const float4*)(w1g + (size_t)lr * H_DIM + k0 + lk4);
            float4 vu = *(const float4*)(w1u + (size_t)lr * H_DIM + k0 + lk4);
            Bg[(lk4 + 0) * 68 + lr] = vg.x;
            Bg[(lk4 + 1) * 68 + lr] = vg.y;
            Bg[(lk4 + 2) * 68 + lr] = vg.z;
            Bg[(lk4 + 3) * 68 + lr] = vg.w;
            Bu[(lk4 + 0) * 68 + lr] = vu.x;
            Bu[(lk4 + 1) * 68 + lr] = vu.y;
            Bu[(lk4 + 2) * 68 + lr] = vu.z;
            Bu[(lk4 + 3) * 68 + lr] = vu.w;
        }
        __syncthreads();

#pragma unroll
        for (int kk = 0; kk < 16; kk++) {
            float4 a0 = *(const float4*)&As[kk * 132 + ty * 8];
            float4 a1 = *(const float4*)&As[kk * 132 + ty * 8 + 4];
            float4 bg = *(const float4*)&Bg[kk * 68 + tx * 4];
            float4 bu = *(const float4*)&Bu[kk * 68 + tx * 4];
            float a[8]  = {a0.x, a0.y, a0.z, a0.w, a1.x, a1.y, a1.z, a1.w};
            float bgv[4] = {bg.x, bg.y, bg.z, bg.w};
            float buv[4] = {bu.x, bu.y, bu.z, bu.w};
#pragma unroll
            for (int i = 0; i < 8; i++)
#pragma unroll
                for (int j = 0; j < 4; j++) {
                    accg[i][j] += a[i] * bgv[j];
                    accu[i][j] += a[i] * buv[j];
                }
        }
        __syncthreads();
    }

    // epilogue: h = silu(gate) * up  -> g_act[slot][n]
    const int slot0 = e * T_TOK + m0;
#pragma unroll
    for (int i = 0; i < 8; i++) {
        int row = ty * 8 + i;
        if (m0 + row < cnt) {
            float4 o;
            float g, u;
            g = accg[i][0]; u = accu[i][0]; o.x = (g / (1.0f + expf(-g))) * u;
            g = accg[i][1]; u = accu[i][1]; o.y = (g / (1.0f + expf(-g))) * u;
            g = accg[i][2]; u = accu[i][2]; o.z = (g / (1.0f + expf(-g))) * u;
            g = accg[i][3]; u = accu[i][3]; o.w = (g / (1.0f + expf(-g))) * u;
            *(float4*)(g_act + (size_t)(slot0 + row) * F_DIM + n0 + tx * 4) = o;
        }
    }
}

// ---------------------------------------------------------------------------
// Kernel 3: GEMM2 (y = act @ w2[e].T) + weighted scatter into out
//   Per block: 128 slots x 128 H-cols, K = F_DIM.
//   grid = (T/128, H/128, E); early-exit on empty M tiles.
// ---------------------------------------------------------------------------
__global__ __launch_bounds__(256, 2)
void gemm2_kernel(const float* __restrict__ w2, float* __restrict__ out) {
    const int e   = blockIdx.z;
    const int cnt = g_cnt[e];
    const int m0  = blockIdx.x * 128;
    if (m0 >= cnt) return;
    const int n0  = blockIdx.y * 128;

    __shared__ float As[16 * 132];
    __shared__ float Bs[16 * 132];
    __shared__ int   stok[128];

    const int tid = threadIdx.x;
    const int tx  = tid & 15;        // 8 cols each
    const int ty  = tid >> 4;        // 8 rows each

    if (tid < 128) {
        int i = m0 + tid;
        stok[tid] = (i < cnt) ? g_tok[e * T_TOK + i] : 0;
    }
    __syncthreads();

    float acc[8][8];
#pragma unroll
    for (int i = 0; i < 8; i++)
#pragma unroll
        for (int j = 0; j < 8; j++) acc[i][j] = 0.0f;

    const float* w2e  = w2 + (size_t)e * H_DIM * F_DIM + (size_t)n0 * F_DIM;
    const float* actb = g_act + (size_t)(e * T_TOK + m0) * F_DIM;

    const int lr  = tid >> 2;        // 0..63
    const int lk4 = (tid & 3) * 4;

    for (int k0 = 0; k0 < F_DIM; k0 += 16) {
#pragma unroll
        for (int r = 0; r < 2; r++) {
            int row = lr + r * 64;
            float4 va = *(const float4*)(actb + (size_t)row * F_DIM + k0 + lk4);
            As[(lk4 + 0) * 132 + row] = va.x;
            As[(lk4 + 1) * 132 + row] = va.y;
            As[(lk4 + 2) * 132 + row] = va.z;
            As[(lk4 + 3) * 132 + row] = va.w;
            float4 vb = *(const float4*)(w2e + (size_t)row * F_DIM + k0 + lk4);
            Bs[(lk4 + 0) * 132 + row] = vb.x;
            Bs[(lk4 + 1) * 132 + row] = vb.y;
            Bs[(lk4 + 2) * 132 + row] = vb.z;
            Bs[(lk4 + 3) * 132 + row] = vb.w;
        }
        __syncthreads();

#pragma unroll
        for (int kk = 0; kk < 16; kk++) {
            float4 a0 = *(const float4*)&As[kk * 132 + ty * 8];
            float4 a1 = *(const float4*)&As[kk * 132 + ty * 8 + 4];
            float4 b0 = *(const float4*)&Bs[kk * 132 + tx * 8];
            float4 b1 = *(const float4*)&Bs[kk * 132 + tx * 8 + 4];
            float a[8] = {a0.x, a0.y, a0.z, a0.w, a1.x, a1.y, a1.z, a1.w};
            float b[8] = {b0.x, b0.y, b0.z, b0.w, b1.x, b1.y, b1.z, b1.w};
#pragma unroll
            for (int i = 0; i < 8; i++)
#pragma unroll
                for (int j = 0; j < 8; j++) acc[i][j] += a[i] * b[j];
        }
        __syncthreads();
    }

    // epilogue: out[token] += w * y   (exactly 2 atomic adds per output element
    // across the whole launch -> bitwise-commutative, deterministic)
#pragma unroll
    for (int i = 0; i < 8; i++) {
        int row = ty * 8 + i;
        if (m0 + row < cnt) {
            float  w    = g_wgt[e * T_TOK + m0 + row];
            float* orow = out + (size_t)stok[row] * H_DIM + n0 + tx * 8;
#pragma unroll
            for (int j = 0; j < 8; j++) {
                atomicAdd(&orow[j], w * acc[i][j]);
            }
        }
    }
}

// ---------------------------------------------------------------------------
// Launch
// ---------------------------------------------------------------------------
extern "C" void kernel_launch(void* const* d_in, const int* in_sizes, int n_in,
                              void* d_out, int out_size) {
    (void)in_sizes; (void)n_in; (void)out_size;
    const float* hidden = (const float*)d_in[0];
    const float* logits = (const float*)d_in[1];
    const float* w1     = (const float*)d_in[2];
    const float* w2     = (const float*)d_in[3];
    float*       out    = (float*)d_out;

    init_kernel<<<2048, 256>>>(out);
    route_kernel<<<T_TOK / 256, 256>>>(logits);

    dim3 g1(T_TOK / 128, F_DIM / 64, E_NUM);   // (64, 22, 8)
    gemm1_kernel<<<g1, 256>>>(hidden, w1);

    dim3 g2(T_TOK / 128, H_DIM / 128, E_NUM);  // (64, 16, 8)
    gemm2_kernel<<<g2, 256>>>(w2, out);
}

// round 10
// speedup vs baseline: 1.8422x; 1.8422x over previous
#include <cuda_runtime.h>
#include <cuda_bf16.h>
#include <stdint.h>
#include <math.h>

// Problem constants
#define T_TOK 8192
#define H_DIM 2048
#define F_DIM 1408
#define E_NUM 8
#define F2    (2 * F_DIM)
#define FH    (F_DIM / 2)          // u32 (bf16 pairs) per act row

// Tiling
#define BK       32
#define RSTRIDE  80                // smem bytes per row: 32 bf16 (64B) + 16B pad
#define A_BYTES  (128 * RSTRIDE)   // 10240
#define B_BYTES  (256 * RSTRIDE)   // 20480
#define STAGE_B  (2 * A_BYTES + 2 * B_BYTES)   // 61440
#define SMEM_TILES_OFF 1024
#define SMEM_TOTAL (SMEM_TILES_OFF + 2 * STAGE_B)   // 123904

// ---------------------------------------------------------------------------
// Static device scratch
// ---------------------------------------------------------------------------
__device__ int   g_cnt[E_NUM];
__device__ int   g_tok[E_NUM * T_TOK];
__device__ float g_wgt[E_NUM * T_TOK];
__device__ __align__(16) unsigned g_act_hi[(size_t)E_NUM * T_TOK * FH];
__device__ __align__(16) unsigned g_act_lo[(size_t)E_NUM * T_TOK * FH];

// ---------------------------------------------------------------------------
// Helpers
// ---------------------------------------------------------------------------
__device__ __forceinline__ uint32_t smem_u32(const void* p) {
    uint32_t a;
    asm("{ .reg .u64 t; cvta.to.shared.u64 t, %1; cvt.u32.u64 %0, t; }"
        : "=r"(a) : "l"(p));
    return a;
}

__device__ __forceinline__ void ldm4(uint32_t* r, uint32_t addr) {
    asm volatile("ldmatrix.sync.aligned.m8n8.x4.shared.b16 {%0,%1,%2,%3}, [%4];"
                 : "=r"(r[0]), "=r"(r[1]), "=r"(r[2]), "=r"(r[3]) : "r"(addr));
}

__device__ __forceinline__ void mma_bf16(float* c, const uint32_t* a,
                                         uint32_t b0, uint32_t b1) {
    asm volatile(
        "mma.sync.aligned.m16n8k16.row.col.f32.bf16.bf16.f32 "
        "{%0,%1,%2,%3}, {%4,%5,%6,%7}, {%8,%9}, {%0,%1,%2,%3};"
        : "+f"(c[0]), "+f"(c[1]), "+f"(c[2]), "+f"(c[3])
        : "r"(a[0]), "r"(a[1]), "r"(a[2]), "r"(a[3]), "r"(b0), "r"(b1));
}

__device__ __forceinline__ void sts128(uint32_t addr, uint32_t r0, uint32_t r1,
                                       uint32_t r2, uint32_t r3) {
    asm volatile("st.shared.v4.b32 [%0], {%1, %2, %3, %4};"
                 :: "r"(addr), "r"(r0), "r"(r1), "r"(r2), "r"(r3) : "memory");
}

// split fp32 -> bf16 hi + bf16 lo (residual); packed pairs, k-even in low half
__device__ __forceinline__ void split2(float a0, float a1, uint32_t& hi, uint32_t& lo) {
    asm("cvt.rn.satfinite.bf16x2.f32 %0, %1, %2;" : "=r"(hi) : "f"(a1), "f"(a0));
    float h0 = __uint_as_float(hi << 16);
    float h1 = __uint_as_float(hi & 0xFFFF0000u);
    float r0 = a0 - h0;
    float r1 = a1 - h1;
    asm("cvt.rn.satfinite.bf16x2.f32 %0, %1, %2;" : "=r"(lo) : "f"(r1), "f"(r0));
}

__device__ __forceinline__ void split8(float4 v0, float4 v1, uint32_t* h, uint32_t* l) {
    split2(v0.x, v0.y, h[0], l[0]);
    split2(v0.z, v0.w, h[1], l[1]);
    split2(v1.x, v1.y, h[2], l[2]);
    split2(v1.z, v1.w, h[3], l[3]);
}

// ---------------------------------------------------------------------------
// Kernel 0 + 1: init / route (proven)
// ---------------------------------------------------------------------------
__global__ void init_kernel(float* __restrict__ out) {
    int idx = blockIdx.x * blockDim.x + threadIdx.x;
    if (idx < E_NUM) g_cnt[idx] = 0;
    const long long n = (long long)T_TOK * H_DIM;
    long long stride = (long long)gridDim.x * blockDim.x;
    for (long long i = idx; i < n; i += stride) out[i] = 0.0f;
}

__global__ void route_kernel(const float* __restrict__ logits) {
    int t = blockIdx.x * blockDim.x + threadIdx.x;
    if (t >= T_TOK) return;
    float l[E_NUM];
#pragma unroll
    for (int i = 0; i < E_NUM; i++) l[i] = logits[t * E_NUM + i];
    int i0 = 0; float v0 = l[0];
#pragma unroll
    for (int i = 1; i < E_NUM; i++) if (l[i] > v0) { v0 = l[i]; i0 = i; }
    int i1 = -1; float v1 = -3.402823466e+38f;
#pragma unroll
    for (int i = 0; i < E_NUM; i++) if (i != i0 && l[i] > v1) { v1 = l[i]; i1 = i; }
    float r  = expf(v1 - v0);
    float w0 = 1.0f / (1.0f + r);
    float w1 = r / (1.0f + r);
    int p0 = atomicAdd(&g_cnt[i0], 1);
    g_tok[i0 * T_TOK + p0] = t; g_wgt[i0 * T_TOK + p0] = w0;
    int p1 = atomicAdd(&g_cnt[i1], 1);
    g_tok[i1 * T_TOK + p1] = t; g_wgt[i1 * T_TOK + p1] = w1;
}

// ---------------------------------------------------------------------------
// Warp-MMA compute for one K-chunk (shared by both GEMMs).
// Per warp: 64(M) x 32(N) tile, K=32, split-bf16 (hh + hl + lh).
// ---------------------------------------------------------------------------
__device__ __forceinline__ void compute_chunk(
    float acc[4][4][4],
    uint32_t aH, uint32_t aL,   // A buf bases + warp-row offset + lane offset
    uint32_t bH, uint32_t bL)   // B buf bases + warp-col offset + lane offset
{
#pragma unroll
    for (int ks = 0; ks < 2; ks++) {
        const uint32_t ko = ks * 32;
        uint32_t b[8];
        ldm4(b,     bH + ko);
        ldm4(b + 4, bH + 16 * RSTRIDE + ko);
        uint32_t a4[4];
#pragma unroll
        for (int mf = 0; mf < 4; mf++) {
            ldm4(a4, aH + mf * 16 * RSTRIDE + ko);
            mma_bf16(acc[mf][0], a4, b[0], b[1]);
            mma_bf16(acc[mf][1], a4, b[2], b[3]);
            mma_bf16(acc[mf][2], a4, b[4], b[5]);
            mma_bf16(acc[mf][3], a4, b[6], b[7]);
            ldm4(a4, aL + mf * 16 * RSTRIDE + ko);
            mma_bf16(acc[mf][0], a4, b[0], b[1]);
            mma_bf16(acc[mf][1], a4, b[2], b[3]);
            mma_bf16(acc[mf][2], a4, b[4], b[5]);
            mma_bf16(acc[mf][3], a4, b[6], b[7]);
        }
        ldm4(b,     bL + ko);
        ldm4(b + 4, bL + 16 * RSTRIDE + ko);
#pragma unroll
        for (int mf = 0; mf < 4; mf++) {
            ldm4(a4, aH + mf * 16 * RSTRIDE + ko);
            mma_bf16(acc[mf][0], a4, b[0], b[1]);
            mma_bf16(acc[mf][1], a4, b[2], b[3]);
            mma_bf16(acc[mf][2], a4, b[4], b[5]);
            mma_bf16(acc[mf][3], a4, b[6], b[7]);
        }
    }
}

// ---------------------------------------------------------------------------
// GEMM1: [128 gathered tokens] x [128 gate + 128 up cols interleaved], K=2048
//   grid = (64, F/128=11, E), 512 threads
// ---------------------------------------------------------------------------
__global__ __launch_bounds__(512, 1)
void gemm1_mma(const float* __restrict__ hidden, const float* __restrict__ w1) {
    const int e   = blockIdx.z;
    const int cnt = g_cnt[e];
    const int m0  = blockIdx.x * 128;
    if (m0 >= cnt) return;
    const int n0t = blockIdx.y * 128;   // f-column base (gate & up)

    extern __shared__ char smem[];
    const uint32_t sbase = smem_u32(smem);
    int* stok = (int*)smem;
    const uint32_t tiles = sbase + SMEM_TILES_OFF;

    const int tid  = threadIdx.x;
    const int lane = tid & 31;
    const int wid  = tid >> 5;
    const int wrow = wid & 1;          // 0..1  -> 64 M rows
    const int wcol = wid >> 1;         // 0..7  -> 32 B-rows

    if (tid < 128) {
        int i = m0 + tid;
        stok[tid] = (i < cnt) ? g_tok[e * T_TOK + i] : 0;
    }
    __syncthreads();

    // loader indices
    const int arow = tid >> 2;            // 0..127
    const int akq  = (tid & 3) * 8;       // fp32 k offset
    const int br   = tid >> 1;            // 0..255 (B smem row)
    const int bkq  = (tid & 1) * 16;
    // B smem row -> w1 global row (gate/up interleaved per 8-row block)
    const int bwc  = br >> 5;
    const int bj   = (br >> 3) & 3;
    const int bln  = br & 7;
    const int fcol = bwc * 16 + (bj >> 1) * 8 + bln;
    const int grow = n0t + fcol + ((bj & 1) ? F_DIM : 0);

    const float* w1e = w1 + (size_t)e * F2 * H_DIM;
    const float* ap  = hidden + (size_t)stok[arow] * H_DIM + akq;
    const float* bp  = w1e + (size_t)grow * H_DIM + bkq;

    // lane offsets for ldmatrix
    const uint32_t a_loff = (uint32_t)((lane & 15) * RSTRIDE + (lane >> 4) * 16);
    const uint32_t b_loff = (uint32_t)(((lane & 7) + ((lane >> 4) & 1) * 8) * RSTRIDE
                                       + ((lane >> 3) & 1) * 16);

    const uint32_t a_srow = (uint32_t)(arow * RSTRIDE + akq * 2);
    const uint32_t b_srow = (uint32_t)(br * RSTRIDE + bkq * 2);

    float acc[4][4][4];
#pragma unroll
    for (int i = 0; i < 4; i++)
#pragma unroll
        for (int j = 0; j < 4; j++)
#pragma unroll
            for (int q = 0; q < 4; q++) acc[i][j][q] = 0.0f;

    float4 af0, af1, bf0, bf1, bf2, bf3;
    // prologue: chunk 0
    af0 = *(const float4*)(ap);     af1 = *(const float4*)(ap + 4);
    bf0 = *(const float4*)(bp);     bf1 = *(const float4*)(bp + 4);
    bf2 = *(const float4*)(bp + 8); bf3 = *(const float4*)(bp + 12);
    {
        const uint32_t s = tiles;
        uint32_t h[4], l[4];
        split8(af0, af1, h, l);
        sts128(s + a_srow, h[0], h[1], h[2], h[3]);
        sts128(s + A_BYTES + a_srow, l[0], l[1], l[2], l[3]);
        const uint32_t bh = s + 2 * A_BYTES, bl = bh + B_BYTES;
        split8(bf0, bf1, h, l);
        sts128(bh + b_srow, h[0], h[1], h[2], h[3]);
        sts128(bl + b_srow, l[0], l[1], l[2], l[3]);
        split8(bf2, bf3, h, l);
        sts128(bh + b_srow + 16, h[0], h[1], h[2], h[3]);
        sts128(bl + b_srow + 16, l[0], l[1], l[2], l[3]);
    }
    __syncthreads();

    const int NC = H_DIM / BK;   // 64
    for (int c = 0; c < NC; c++) {
        if (c + 1 < NC) {
            ap += BK; bp += BK;
            af0 = *(const float4*)(ap);     af1 = *(const float4*)(ap + 4);
            bf0 = *(const float4*)(bp);     bf1 = *(const float4*)(bp + 4);
            bf2 = *(const float4*)(bp + 8); bf3 = *(const float4*)(bp + 12);
        }
        const uint32_t s = tiles + (uint32_t)(c & 1) * STAGE_B;
        compute_chunk(acc,
            s + (uint32_t)(wrow * 64) * RSTRIDE + a_loff,
            s + A_BYTES + (uint32_t)(wrow * 64) * RSTRIDE + a_loff,
            s + 2 * A_BYTES + (uint32_t)(wcol * 32) * RSTRIDE + b_loff,
            s + 2 * A_BYTES + B_BYTES + (uint32_t)(wcol * 32) * RSTRIDE + b_loff);
        __syncthreads();
        if (c + 1 < NC) {
            const uint32_t d = tiles + (uint32_t)((c + 1) & 1) * STAGE_B;
            uint32_t h[4], l[4];
            split8(af0, af1, h, l);
            sts128(d + a_srow, h[0], h[1], h[2], h[3]);
            sts128(d + A_BYTES + a_srow, l[0], l[1], l[2], l[3]);
            const uint32_t bh = d + 2 * A_BYTES, bl = bh + B_BYTES;
            split8(bf0, bf1, h, l);
            sts128(bh + b_srow, h[0], h[1], h[2], h[3]);
            sts128(bl + b_srow, l[0], l[1], l[2], l[3]);
            split8(bf2, bf3, h, l);
            sts128(bh + b_srow + 16, h[0], h[1], h[2], h[3]);
            sts128(bl + b_srow + 16, l[0], l[1], l[2], l[3]);
            __syncthreads();
        }
    }

    // epilogue: silu(gate)*up -> g_act hi/lo
    const int g   = lane >> 2;
    const int tig = lane & 3;
    const int fpair_base = (n0t + wcol * 16) >> 1;   // u32 index base
#pragma unroll
    for (int mf = 0; mf < 4; mf++) {
        const int r0 = wrow * 64 + mf * 16 + g;
        const int r1 = r0 + 8;
#pragma unroll
        for (int p = 0; p < 2; p++) {
            const int ci = fpair_base + p * 4 + tig;
            // rows r0 (c0,c1), r1 (c2,c3)
            if (m0 + r0 < cnt) {
                float gg0 = acc[mf][2*p][0],   gg1 = acc[mf][2*p][1];
                float uu0 = acc[mf][2*p+1][0], uu1 = acc[mf][2*p+1][1];
                float a0 = (gg0 / (1.0f + expf(-gg0))) * uu0;
                float a1 = (gg1 / (1.0f + expf(-gg1))) * uu1;
                uint32_t hi, lo;
                split2(a0, a1, hi, lo);
                size_t idx = (size_t)(e * T_TOK + m0 + r0) * FH + ci;
                g_act_hi[idx] = hi; g_act_lo[idx] = lo;
            }
            if (m0 + r1 < cnt) {
                float gg0 = acc[mf][2*p][2],   gg1 = acc[mf][2*p][3];
                float uu0 = acc[mf][2*p+1][2], uu1 = acc[mf][2*p+1][3];
                float a0 = (gg0 / (1.0f + expf(-gg0))) * uu0;
                float a1 = (gg1 / (1.0f + expf(-gg1))) * uu1;
                uint32_t hi, lo;
                split2(a0, a1, hi, lo);
                size_t idx = (size_t)(e * T_TOK + m0 + r1) * FH + ci;
                g_act_hi[idx] = hi; g_act_lo[idx] = lo;
            }
        }
    }
}

// ---------------------------------------------------------------------------
// GEMM2: [128 slots] x [256 H cols], K=1408; weighted atomic scatter into out
//   grid = (64, H/256=8, E), 512 threads
// ---------------------------------------------------------------------------
__global__ __launch_bounds__(512, 1)
void gemm2_mma(const float* __restrict__ w2, float* __restrict__ out) {
    const int e   = blockIdx.z;
    const int cnt = g_cnt[e];
    const int m0  = blockIdx.x * 128;
    if (m0 >= cnt) return;
    const int n0  = blockIdx.y * 256;

    extern __shared__ char smem[];
    const uint32_t sbase = smem_u32(smem);
    int* stok = (int*)smem;
    const uint32_t tiles = sbase + SMEM_TILES_OFF;

    const int tid  = threadIdx.x;
    const int lane = tid & 31;
    const int wid  = tid >> 5;
    const int wrow = wid & 1;
    const int wcol = wid >> 1;

    if (tid < 128) {
        int i = m0 + tid;
        stok[tid] = (i < cnt) ? g_tok[e * T_TOK + i] : 0;
    }
    __syncthreads();

    // A loader: act bf16 pairs (already split)
    const int arow = tid >> 2;            // 0..127
    const int akq4 = (tid & 3) * 4;       // u32 offset within row chunk
    const size_t aslot = (size_t)(e * T_TOK + m0 + arow) * FH;
    // B loader: w2 fp32
    const int br  = tid >> 1;             // 0..255
    const int bkq = (tid & 1) * 16;
    const float* w2e = w2 + (size_t)e * H_DIM * F_DIM;
    const float* bp  = w2e + (size_t)(n0 + br) * F_DIM + bkq;

    const uint32_t a_loff = (uint32_t)((lane & 15) * RSTRIDE + (lane >> 4) * 16);
    const uint32_t b_loff = (uint32_t)(((lane & 7) + ((lane >> 4) & 1) * 8) * RSTRIDE
                                       + ((lane >> 3) & 1) * 16);
    const uint32_t a_srow = (uint32_t)(arow * RSTRIDE + akq4 * 4);
    const uint32_t b_srow = (uint32_t)(br * RSTRIDE + bkq * 2);

    float acc[4][4][4];
#pragma unroll
    for (int i = 0; i < 4; i++)
#pragma unroll
        for (int j = 0; j < 4; j++)
#pragma unroll
            for (int q = 0; q < 4; q++) acc[i][j][q] = 0.0f;

    uint4 ah, al;
    float4 bf0, bf1, bf2, bf3;
    ah = *(const uint4*)(g_act_hi + aslot + akq4);
    al = *(const uint4*)(g_act_lo + aslot + akq4);
    bf0 = *(const float4*)(bp);     bf1 = *(const float4*)(bp + 4);
    bf2 = *(const float4*)(bp + 8); bf3 = *(const float4*)(bp + 12);
    {
        const uint32_t s = tiles;
        sts128(s + a_srow, ah.x, ah.y, ah.z, ah.w);
        sts128(s + A_BYTES + a_srow, al.x, al.y, al.z, al.w);
        const uint32_t bh = s + 2 * A_BYTES, bl = bh + B_BYTES;
        uint32_t h[4], l[4];
        split8(bf0, bf1, h, l);
        sts128(bh + b_srow, h[0], h[1], h[2], h[3]);
        sts128(bl + b_srow, l[0], l[1], l[2], l[3]);
        split8(bf2, bf3, h, l);
        sts128(bh + b_srow + 16, h[0], h[1], h[2], h[3]);
        sts128(bl + b_srow + 16, l[0], l[1], l[2], l[3]);
    }
    __syncthreads();

    const int NC = F_DIM / BK;   // 44
    for (int c = 0; c < NC; c++) {
        if (c + 1 < NC) {
            bp += BK;
            size_t aidx = aslot + (size_t)(c + 1) * (BK / 2) + akq4;
            ah = *(const uint4*)(g_act_hi + aidx);
            al = *(const uint4*)(g_act_lo + aidx);
            bf0 = *(const float4*)(bp);     bf1 = *(const float4*)(bp + 4);
            bf2 = *(const float4*)(bp + 8); bf3 = *(const float4*)(bp + 12);
        }
        const uint32_t s = tiles + (uint32_t)(c & 1) * STAGE_B;
        compute_chunk(acc,
            s + (uint32_t)(wrow * 64) * RSTRIDE + a_loff,
            s + A_BYTES + (uint32_t)(wrow * 64) * RSTRIDE + a_loff,
            s + 2 * A_BYTES + (uint32_t)(wcol * 32) * RSTRIDE + b_loff,
            s + 2 * A_BYTES + B_BYTES + (uint32_t)(wcol * 32) * RSTRIDE + b_loff);
        __syncthreads();
        if (c + 1 < NC) {
            const uint32_t d = tiles + (uint32_t)((c + 1) & 1) * STAGE_B;
            sts128(d + a_srow, ah.x, ah.y, ah.z, ah.w);
            sts128(d + A_BYTES + a_srow, al.x, al.y, al.z, al.w);
            const uint32_t bh = d + 2 * A_BYTES, bl = bh + B_BYTES;
            uint32_t h[4], l[4];
            split8(bf0, bf1, h, l);
            sts128(bh + b_srow, h[0], h[1], h[2], h[3]);
            sts128(bl + b_srow, l[0], l[1], l[2], l[3]);
            split8(bf2, bf3, h, l);
            sts128(bh + b_srow + 16, h[0], h[1], h[2], h[3]);
            sts128(bl + b_srow + 16, l[0], l[1], l[2], l[3]);
            __syncthreads();
        }
    }

    // epilogue: out[token] += w * y (exactly 2 atomics per element across grid)
    const int g   = lane >> 2;
    const int tig = lane & 3;
#pragma unroll
    for (int mf = 0; mf < 4; mf++) {
        const int r0 = wrow * 64 + mf * 16 + g;
        const int r1 = r0 + 8;
        const bool v0 = (m0 + r0) < cnt;
        const bool v1 = (m0 + r1) < cnt;
        const float w0 = v0 ? g_wgt[e * T_TOK + m0 + r0] : 0.0f;
        const float w1 = v1 ? g_wgt[e * T_TOK + m0 + r1] : 0.0f;
        float* o0 = out + (size_t)stok[r0] * H_DIM;
        float* o1 = out + (size_t)stok[r1] * H_DIM;
#pragma unroll
        for (int nf = 0; nf < 4; nf++) {
            const int col = n0 + wcol * 32 + nf * 8 + 2 * tig;
            if (v0) {
                atomicAdd(o0 + col,     w0 * acc[mf][nf][0]);
                atomicAdd(o0 + col + 1, w0 * acc[mf][nf][1]);
            }
            if (v1) {
                atomicAdd(o1 + col,     w1 * acc[mf][nf][2]);
                atomicAdd(o1 + col + 1, w1 * acc[mf][nf][3]);
            }
        }
    }
}

// ---------------------------------------------------------------------------
// Launch
// ---------------------------------------------------------------------------
extern "C" void kernel_launch(void* const* d_in, const int* in_sizes, int n_in,
                              void* d_out, int out_size) {
    (void)in_sizes; (void)n_in; (void)out_size;
    const float* hidden = (const float*)d_in[0];
    const float* logits = (const float*)d_in[1];
    const float* w1     = (const float*)d_in[2];
    const float* w2     = (const float*)d_in[3];
    float*       out    = (float*)d_out;

    cudaFuncSetAttribute(gemm1_mma, cudaFuncAttributeMaxDynamicSharedMemorySize, SMEM_TOTAL);
    cudaFuncSetAttribute(gemm2_mma, cudaFuncAttributeMaxDynamicSharedMemorySize, SMEM_TOTAL);

    init_kernel<<<2048, 256>>>(out);
    route_kernel<<<T_TOK / 256, 256>>>(logits);

    dim3 g1(T_TOK / 128, F_DIM / 128, E_NUM);   // (64, 11, 8)
    gemm1_mma<<<g1, 512, SMEM_TOTAL>>>(hidden, w1);

    dim3 g2(T_TOK / 128, H_DIM / 256, E_NUM);   // (64, 8, 8)
    gemm2_mma<<<g2, 512, SMEM_TOTAL>>>(w2, out);
}

// round 11
// speedup vs baseline: 2.1669x; 1.1762x over previous
#include <cuda_runtime.h>
#include <cuda_bf16.h>
#include <stdint.h>
#include <math.h>

// Problem constants
#define T_TOK 8192
#define H_DIM 2048
#define F_DIM 1408
#define E_NUM 8
#define F2    (2 * F_DIM)
#define FH    (F_DIM / 2)          // u32 (bf16 pairs) per act row

// Tiling
#define BK       32
#define RSTRIDE  80                // smem bytes per row: 32 bf16 (64B) + 16B pad
#define A_BYTES  (128 * RSTRIDE)   // 10240
#define B_BYTES  (256 * RSTRIDE)   // 20480
#define STAGE_B  (2 * A_BYTES + 2 * B_BYTES)   // 61440
#define SMEM_TILES_OFF 1024
#define SMEM_TOTAL (SMEM_TILES_OFF + 3 * STAGE_B)   // 185344 (3-stage)

// ---------------------------------------------------------------------------
// Static device scratch
// ---------------------------------------------------------------------------
__device__ int   g_cnt[E_NUM];
__device__ int   g_tok[E_NUM * T_TOK];
__device__ float g_wgt[E_NUM * T_TOK];
__device__ __align__(16) unsigned g_act_hi[(size_t)E_NUM * T_TOK * FH];
__device__ __align__(16) unsigned g_act_lo[(size_t)E_NUM * T_TOK * FH];

// ---------------------------------------------------------------------------
// Helpers
// ---------------------------------------------------------------------------
__device__ __forceinline__ uint32_t smem_u32(const void* p) {
    uint32_t a;
    asm("{ .reg .u64 t; cvta.to.shared.u64 t, %1; cvt.u32.u64 %0, t; }"
        : "=r"(a) : "l"(p));
    return a;
}

__device__ __forceinline__ void ldm4(uint32_t* r, uint32_t addr) {
    asm volatile("ldmatrix.sync.aligned.m8n8.x4.shared.b16 {%0,%1,%2,%3}, [%4];"
                 : "=r"(r[0]), "=r"(r[1]), "=r"(r[2]), "=r"(r[3]) : "r"(addr));
}

__device__ __forceinline__ void mma_bf16(float* c, const uint32_t* a,
                                         uint32_t b0, uint32_t b1) {
    asm volatile(
        "mma.sync.aligned.m16n8k16.row.col.f32.bf16.bf16.f32 "
        "{%0,%1,%2,%3}, {%4,%5,%6,%7}, {%8,%9}, {%0,%1,%2,%3};"
        : "+f"(c[0]), "+f"(c[1]), "+f"(c[2]), "+f"(c[3])
        : "r"(a[0]), "r"(a[1]), "r"(a[2]), "r"(a[3]), "r"(b0), "r"(b1));
}

__device__ __forceinline__ void sts128(uint32_t addr, uint32_t r0, uint32_t r1,
                                       uint32_t r2, uint32_t r3) {
    asm volatile("st.shared.v4.b32 [%0], {%1, %2, %3, %4};"
                 :: "r"(addr), "r"(r0), "r"(r1), "r"(r2), "r"(r3) : "memory");
}

// split fp32 -> bf16 hi + bf16 lo (residual); packed pairs, k-even in low half
__device__ __forceinline__ void split2(float a0, float a1, uint32_t& hi, uint32_t& lo) {
    asm("cvt.rn.satfinite.bf16x2.f32 %0, %1, %2;" : "=r"(hi) : "f"(a1), "f"(a0));
    float h0 = __uint_as_float(hi << 16);
    float h1 = __uint_as_float(hi & 0xFFFF0000u);
    float r0 = a0 - h0;
    float r1 = a1 - h1;
    asm("cvt.rn.satfinite.bf16x2.f32 %0, %1, %2;" : "=r"(lo) : "f"(r1), "f"(r0));
}

__device__ __forceinline__ void split8(float4 v0, float4 v1, uint32_t* h, uint32_t* l) {
    split2(v0.x, v0.y, h[0], l[0]);
    split2(v0.z, v0.w, h[1], l[1]);
    split2(v1.x, v1.y, h[2], l[2]);
    split2(v1.z, v1.w, h[3], l[3]);
}

// ---------------------------------------------------------------------------
// Kernel 0 + 1: init / route (proven)
// ---------------------------------------------------------------------------
__global__ void init_kernel(float* __restrict__ out) {
    int idx = blockIdx.x * blockDim.x + threadIdx.x;
    if (idx < E_NUM) g_cnt[idx] = 0;
    const long long n = (long long)T_TOK * H_DIM;
    long long stride = (long long)gridDim.x * blockDim.x;
    for (long long i = idx; i < n; i += stride) out[i] = 0.0f;
}

__global__ void route_kernel(const float* __restrict__ logits) {
    int t = blockIdx.x * blockDim.x + threadIdx.x;
    if (t >= T_TOK) return;
    float l[E_NUM];
#pragma unroll
    for (int i = 0; i < E_NUM; i++) l[i] = logits[t * E_NUM + i];
    int i0 = 0; float v0 = l[0];
#pragma unroll
    for (int i = 1; i < E_NUM; i++) if (l[i] > v0) { v0 = l[i]; i0 = i; }
    int i1 = -1; float v1 = -3.402823466e+38f;
#pragma unroll
    for (int i = 0; i < E_NUM; i++) if (i != i0 && l[i] > v1) { v1 = l[i]; i1 = i; }
    float r  = expf(v1 - v0);
    float w0 = 1.0f / (1.0f + r);
    float w1 = r / (1.0f + r);
    int p0 = atomicAdd(&g_cnt[i0], 1);
    g_tok[i0 * T_TOK + p0] = t; g_wgt[i0 * T_TOK + p0] = w0;
    int p1 = atomicAdd(&g_cnt[i1], 1);
    g_tok[i1 * T_TOK + p1] = t; g_wgt[i1 * T_TOK + p1] = w1;
}

// ---------------------------------------------------------------------------
// Warp-MMA compute for one K-chunk. Per warp: 64(M) x 64(N), K=32.
// Split-bf16: hh + lh + hl terms, fp32 accum. B frags loaded once per k-slice.
// ---------------------------------------------------------------------------
__device__ __forceinline__ void compute_chunk(
    float acc[4][8][4],
    uint32_t aH, uint32_t aL,   // A hi/lo bases (+warp row offset +lane offset)
    uint32_t bH, uint32_t bL)   // B hi/lo bases (+warp col offset +lane offset)
{
#pragma unroll
    for (int ks = 0; ks < 2; ks++) {
        const uint32_t ko = ks * 32;
        uint32_t bh[16], bl[16];
#pragma unroll
        for (int t = 0; t < 4; t++) ldm4(bh + 4 * t, bH + t * 16 * RSTRIDE + ko);
#pragma unroll
        for (int t = 0; t < 4; t++) ldm4(bl + 4 * t, bL + t * 16 * RSTRIDE + ko);
#pragma unroll
        for (int mf = 0; mf < 4; mf++) {
            uint32_t ah4[4], al4[4];
            ldm4(ah4, aH + mf * 16 * RSTRIDE + ko);
            ldm4(al4, aL + mf * 16 * RSTRIDE + ko);
#pragma unroll
            for (int nf = 0; nf < 8; nf++)
                mma_bf16(acc[mf][nf], ah4, bh[2 * nf], bh[2 * nf + 1]);
#pragma unroll
            for (int nf = 0; nf < 8; nf++)
                mma_bf16(acc[mf][nf], al4, bh[2 * nf], bh[2 * nf + 1]);
#pragma unroll
            for (int nf = 0; nf < 8; nf++)
                mma_bf16(acc[mf][nf], ah4, bl[2 * nf], bl[2 * nf + 1]);
        }
    }
}

// ---------------------------------------------------------------------------
// GEMM1: [128 gathered tokens] x [128 gate + 128 up cols], K=2048
//   grid = (64, 11, 8), 256 threads (8 warps, 64x64 warp tiles)
// ---------------------------------------------------------------------------
__device__ __forceinline__ void g1_load(const float* ap, const float* bp, int k0,
                                        float4* A, float4* B) {
#pragma unroll
    for (int i = 0; i < 4; i++) A[i] = *(const float4*)(ap + k0 + i * 4);
#pragma unroll
    for (int i = 0; i < 8; i++) B[i] = *(const float4*)(bp + k0 + i * 4);
}

__device__ __forceinline__ void g1_sts(uint32_t s, uint32_t a_srow, uint32_t b_srow,
                                       const float4* A, const float4* B) {
    uint32_t h[4], l[4];
    split8(A[0], A[1], h, l);
    sts128(s + a_srow, h[0], h[1], h[2], h[3]);
    sts128(s + A_BYTES + a_srow, l[0], l[1], l[2], l[3]);
    split8(A[2], A[3], h, l);
    sts128(s + a_srow + 16, h[0], h[1], h[2], h[3]);
    sts128(s + A_BYTES + a_srow + 16, l[0], l[1], l[2], l[3]);
    const uint32_t bh = s + 2 * A_BYTES, bl = bh + B_BYTES;
#pragma unroll
    for (int q = 0; q < 4; q++) {
        split8(B[2 * q], B[2 * q + 1], h, l);
        sts128(bh + b_srow + q * 16, h[0], h[1], h[2], h[3]);
        sts128(bl + b_srow + q * 16, l[0], l[1], l[2], l[3]);
    }
}

__global__ void gemm1_mma(const float* __restrict__ hidden, const float* __restrict__ w1) {
    const int e   = blockIdx.z;
    const int cnt = g_cnt[e];
    const int m0  = blockIdx.x * 128;
    if (m0 >= cnt) return;
    const int n0t = blockIdx.y * 128;   // f-column base

    extern __shared__ char smem[];
    const uint32_t sbase = smem_u32(smem);
    int* stok = (int*)smem;
    const uint32_t tiles = sbase + SMEM_TILES_OFF;

    const int tid  = threadIdx.x;
    const int lane = tid & 31;
    const int wid  = tid >> 5;
    const int wrow = wid & 1;          // M: wrow*64
    const int wcol = wid >> 1;         // N: wcol*64 smem B rows (= 32 f cols)

    if (tid < 128) {
        int i = m0 + tid;
        stok[tid] = (i < cnt) ? g_tok[e * T_TOK + i] : 0;
    }
    __syncthreads();

    // Loaders (256 threads)
    const int arow = tid >> 1;             // 0..127
    const int akq  = (tid & 1) * 16;       // fp32 k offset 0/16
    const int brow = tid;                  // 0..255 smem B row
    // smem B row -> w1 global row (gate/up interleaved per 8-row block)
    const int bj   = (brow >> 3) & 7;
    const int fcol = n0t + (brow >> 6) * 32 + (bj >> 1) * 8 + (brow & 7);
    const int grow = fcol + ((bj & 1) ? F_DIM : 0);

    const float* w1e = w1 + (size_t)e * F2 * H_DIM;
    const float* ap  = hidden + (size_t)stok[arow] * H_DIM + akq;
    const float* bp  = w1e + (size_t)grow * H_DIM;

    const uint32_t a_srow = (uint32_t)(arow * RSTRIDE + akq * 2);
    const uint32_t b_srow = (uint32_t)(brow * RSTRIDE);

    // ldmatrix lane offsets (validated mapping)
    const uint32_t a_loff = (uint32_t)((lane & 15) * RSTRIDE + (lane >> 4) * 16)
                          + (uint32_t)(wrow * 64) * RSTRIDE;
    const uint32_t b_loff = (uint32_t)(((lane & 7) + ((lane >> 4) & 1) * 8) * RSTRIDE
                                       + ((lane >> 3) & 1) * 16)
                          + (uint32_t)(wcol * 64) * RSTRIDE;

    float acc[4][8][4];
#pragma unroll
    for (int i = 0; i < 4; i++)
#pragma unroll
        for (int j = 0; j < 8; j++)
#pragma unroll
            for (int q = 0; q < 4; q++) acc[i][j][q] = 0.0f;

    float4 Ar[4], Br[8];
    g1_load(ap, bp, 0, Ar, Br);
    g1_sts(tiles, a_srow, b_srow, Ar, Br);
    g1_load(ap, bp, BK, Ar, Br);
    __syncthreads();

    const int NC = H_DIM / BK;   // 64
    for (int c = 0; c < NC; c++) {
        const uint32_t rb = tiles + (uint32_t)(c % 3) * STAGE_B;
        if (c + 1 < NC) {
            const uint32_t wb = tiles + (uint32_t)((c + 1) % 3) * STAGE_B;
            g1_sts(wb, a_srow, b_srow, Ar, Br);
        }
        if (c + 2 < NC) g1_load(ap, bp, (c + 2) * BK, Ar, Br);
        compute_chunk(acc,
                      rb + a_loff, rb + A_BYTES + a_loff,
                      rb + 2 * A_BYTES + b_loff, rb + 2 * A_BYTES + B_BYTES + b_loff);
        __syncthreads();
    }

    // epilogue: silu(gate)*up -> g_act hi/lo (gate=even nf, up=odd nf)
    const int g   = lane >> 2;
    const int tig = lane & 3;
#pragma unroll
    for (int mf = 0; mf < 4; mf++) {
        const int r0 = wrow * 64 + mf * 16 + g;
        const int r1 = r0 + 8;
#pragma unroll
        for (int p = 0; p < 4; p++) {
            const int ci = ((n0t + wcol * 32 + p * 8) >> 1) + tig;
            if (m0 + r0 < cnt) {
                float g0 = acc[mf][2*p][0],   g1v = acc[mf][2*p][1];
                float u0 = acc[mf][2*p+1][0], u1  = acc[mf][2*p+1][1];
                float a0 = (g0 / (1.0f + expf(-g0))) * u0;
                float a1 = (g1v / (1.0f + expf(-g1v))) * u1;
                uint32_t hi, lo;
                split2(a0, a1, hi, lo);
                size_t idx = (size_t)(e * T_TOK + m0 + r0) * FH + ci;
                g_act_hi[idx] = hi; g_act_lo[idx] = lo;
            }
            if (m0 + r1 < cnt) {
                float g0 = acc[mf][2*p][2],   g1v = acc[mf][2*p][3];
                float u0 = acc[mf][2*p+1][2], u1  = acc[mf][2*p+1][3];
                float a0 = (g0 / (1.0f + expf(-g0))) * u0;
                float a1 = (g1v / (1.0f + expf(-g1v))) * u1;
                uint32_t hi, lo;
                split2(a0, a1, hi, lo);
                size_t idx = (size_t)(e * T_TOK + m0 + r1) * FH + ci;
                g_act_hi[idx] = hi; g_act_lo[idx] = lo;
            }
        }
    }
}

// ---------------------------------------------------------------------------
// GEMM2: [128 slots] x [256 H cols], K=1408; weighted atomic scatter into out
//   grid = (64, 8, 8), 256 threads (8 warps, 64x64 warp tiles)
// ---------------------------------------------------------------------------
__device__ __forceinline__ void g2_load(const unsigned* hp, const unsigned* lp,
                                        const float* bp, int c,
                                        uint4* AH, uint4* AL, float4* B) {
    AH[0] = *(const uint4*)(hp + c * 16);
    AH[1] = *(const uint4*)(hp + c * 16 + 4);
    AL[0] = *(const uint4*)(lp + c * 16);
    AL[1] = *(const uint4*)(lp + c * 16 + 4);
#pragma unroll
    for (int i = 0; i < 8; i++) B[i] = *(const float4*)(bp + c * BK + i * 4);
}

__device__ __forceinline__ void g2_sts(uint32_t s, uint32_t a_srow, uint32_t b_srow,
                                       const uint4* AH, const uint4* AL, const float4* B) {
    sts128(s + a_srow,      AH[0].x, AH[0].y, AH[0].z, AH[0].w);
    sts128(s + a_srow + 16, AH[1].x, AH[1].y, AH[1].z, AH[1].w);
    sts128(s + A_BYTES + a_srow,      AL[0].x, AL[0].y, AL[0].z, AL[0].w);
    sts128(s + A_BYTES + a_srow + 16, AL[1].x, AL[1].y, AL[1].z, AL[1].w);
    const uint32_t bh = s + 2 * A_BYTES, bl = bh + B_BYTES;
    uint32_t h[4], l[4];
#pragma unroll
    for (int q = 0; q < 4; q++) {
        split8(B[2 * q], B[2 * q + 1], h, l);
        sts128(bh + b_srow + q * 16, h[0], h[1], h[2], h[3]);
        sts128(bl + b_srow + q * 16, l[0], l[1], l[2], l[3]);
    }
}

__global__ void gemm2_mma(const float* __restrict__ w2, float* __restrict__ out) {
    const int e   = blockIdx.z;
    const int cnt = g_cnt[e];
    const int m0  = blockIdx.x * 128;
    if (m0 >= cnt) return;
    const int n0  = blockIdx.y * 256;

    extern __shared__ char smem[];
    const uint32_t sbase = smem_u32(smem);
    int* stok = (int*)smem;
    const uint32_t tiles = sbase + SMEM_TILES_OFF;

    const int tid  = threadIdx.x;
    const int lane = tid & 31;
    const int wid  = tid >> 5;
    const int wrow = wid & 1;
    const int wcol = wid >> 1;

    if (tid < 128) {
        int i = m0 + tid;
        stok[tid] = (i < cnt) ? g_tok[e * T_TOK + i] : 0;
    }
    __syncthreads();

    const int arow = tid >> 1;            // 0..127
    const int aq8  = (tid & 1) * 8;       // u32 offset 0/8
    const size_t aslot = (size_t)(e * T_TOK + m0 + arow) * FH + aq8;
    const unsigned* hp = g_act_hi + aslot;
    const unsigned* lp = g_act_lo + aslot;
    const float* w2e = w2 + (size_t)e * H_DIM * F_DIM;
    const float* bp  = w2e + (size_t)(n0 + tid) * F_DIM;

    const uint32_t a_srow = (uint32_t)(arow * RSTRIDE + aq8 * 4);
    const uint32_t b_srow = (uint32_t)(tid * RSTRIDE);

    const uint32_t a_loff = (uint32_t)((lane & 15) * RSTRIDE + (lane >> 4) * 16)
                          + (uint32_t)(wrow * 64) * RSTRIDE;
    const uint32_t b_loff = (uint32_t)(((lane & 7) + ((lane >> 4) & 1) * 8) * RSTRIDE
                                       + ((lane >> 3) & 1) * 16)
                          + (uint32_t)(wcol * 64) * RSTRIDE;

    float acc[4][8][4];
#pragma unroll
    for (int i = 0; i < 4; i++)
#pragma unroll
        for (int j = 0; j < 8; j++)
#pragma unroll
            for (int q = 0; q < 4; q++) acc[i][j][q] = 0.0f;

    uint4 AH[2], AL[2];
    float4 Br[8];
    g2_load(hp, lp, bp, 0, AH, AL, Br);
    g2_sts(tiles, a_srow, b_srow, AH, AL, Br);
    g2_load(hp, lp, bp, 1, AH, AL, Br);
    __syncthreads();

    const int NC = F_DIM / BK;   // 44
    for (int c = 0; c < NC; c++) {
        const uint32_t rb = tiles + (uint32_t)(c % 3) * STAGE_B;
        if (c + 1 < NC) {
            const uint32_t wb = tiles + (uint32_t)((c + 1) % 3) * STAGE_B;
            g2_sts(wb, a_srow, b_srow, AH, AL, Br);
        }
        if (c + 2 < NC) g2_load(hp, lp, bp, c + 2, AH, AL, Br);
        compute_chunk(acc,
                      rb + a_loff, rb + A_BYTES + a_loff,
                      rb + 2 * A_BYTES + b_loff, rb + 2 * A_BYTES + B_BYTES + b_loff);
        __syncthreads();
    }

    // epilogue: out[token] += w * y (exactly 2 atomics per element across grid)
    const int g   = lane >> 2;
    const int tig = lane & 3;
#pragma unroll
    for (int mf = 0; mf < 4; mf++) {
        const int r0 = wrow * 64 + mf * 16 + g;
        const int r1 = r0 + 8;
        const bool v0 = (m0 + r0) < cnt;
        const bool v1 = (m0 + r1) < cnt;
        const float w0 = v0 ? g_wgt[e * T_TOK + m0 + r0] : 0.0f;
        const float w1 = v1 ? g_wgt[e * T_TOK + m0 + r1] : 0.0f;
        float* o0 = out + (size_t)stok[r0] * H_DIM;
        float* o1 = out + (size_t)stok[r1] * H_DIM;
#pragma unroll
        for (int nf = 0; nf < 8; nf++) {
            const int col = n0 + wcol * 64 + nf * 8 + 2 * tig;
            if (v0) {
                atomicAdd(o0 + col,     w0 * acc[mf][nf][0]);
                atomicAdd(o0 + col + 1, w0 * acc[mf][nf][1]);
            }
            if (v1) {
                atomicAdd(o1 + col,     w1 * acc[mf][nf][2]);
                atomicAdd(o1 + col + 1, w1 * acc[mf][nf][3]);
            }
        }
    }
}

// ---------------------------------------------------------------------------
// Launch
// ---------------------------------------------------------------------------
extern "C" void kernel_launch(void* const* d_in, const int* in_sizes, int n_in,
                              void* d_out, int out_size) {
    (void)in_sizes; (void)n_in; (void)out_size;
    const float* hidden = (const float*)d_in[0];
    const float* logits = (const float*)d_in[1];
    const float* w1     = (const float*)d_in[2];
    const float* w2     = (const float*)d_in[3];
    float*       out    = (float*)d_out;

    cudaFuncSetAttribute(gemm1_mma, cudaFuncAttributeMaxDynamicSharedMemorySize, SMEM_TOTAL);
    cudaFuncSetAttribute(gemm2_mma, cudaFuncAttributeMaxDynamicSharedMemorySize, SMEM_TOTAL);

    init_kernel<<<2048, 256>>>(out);
    route_kernel<<<T_TOK / 256, 256>>>(logits);

    dim3 g1(T_TOK / 128, F_DIM / 128, E_NUM);   // (64, 11, 8)
    gemm1_mma<<<g1, 256, SMEM_TOTAL>>>(hidden, w1);

    dim3 g2(T_TOK / 128, H_DIM / 256, E_NUM);   // (64, 8, 8)
    gemm2_mma<<<g2, 256, SMEM_TOTAL>>>(w2, out);
}